// round 4
// baseline (speedup 1.0000x reference)
#include <cuda_runtime.h>

// Shapes fixed by the problem's setup_inputs.
#define B_     16
#define N_     1024
#define M_     1024
#define CIN_   7
#define C_     8
#define COUT_  16
#define TM_    128     // m-values per block
#define TN_    128     // n-tile size per half
#define THREADS_ 256   // 2 halves of 128 threads, each half covers N/2
#define EPS_   1e-8f

__device__ __forceinline__ float ex2f(float v) {
    float r; asm("ex2.approx.f32 %0, %1;" : "=f"(r) : "f"(v)); return r;
}
__device__ __forceinline__ unsigned long long pack2(float lo, float hi) {
    unsigned long long r;
    asm("mov.b64 %0, {%1, %2};" : "=l"(r) : "f"(lo), "f"(hi));
    return r;
}
__device__ __forceinline__ void unpack2(unsigned long long v, float& lo, float& hi) {
    asm("mov.b64 {%0, %1}, %2;" : "=f"(lo), "=f"(hi) : "l"(v));
}
// Packed dual-FMA (Blackwell f32x2): two independent rn-FMAs in one instruction.
__device__ __forceinline__ unsigned long long fma2(unsigned long long a,
                                                   unsigned long long b,
                                                   unsigned long long c) {
    unsigned long long d;
    asm("fma.rn.f32x2 %0, %1, %2, %3;" : "=l"(d) : "l"(a), "l"(b), "l"(c));
    return d;
}

__global__ __launch_bounds__(THREADS_, 1)
void convdeepset_kernel(const float* __restrict__ x,     // [B, N]
                        const float* __restrict__ y,     // [B, N, CIN]
                        const float* __restrict__ t,     // [B, M]
                        const float* __restrict__ sigma, // [C]
                        const float* __restrict__ w,     // [COUT, C]
                        const float* __restrict__ bias,  // [COUT]
                        float* __restrict__ out)         // [B, M, COUT]
{
    __shared__ float2     sxa[2][TN_];     // {x, k2*x^2}
    __shared__ ulonglong2 syA[2][TN_];     // packed {1,y0 | y1,y2}
    __shared__ ulonglong2 syB[2][TN_];     // packed {y3,y4 | y5,y6}
    __shared__ float      sacc[TM_][C_];   // half-1 partials
    __shared__ float      sw[COUT_ * C_];
    __shared__ float      sb[COUT_];

    const int b   = blockIdx.y;
    const int m0  = blockIdx.x * TM_;
    const int tid = threadIdx.x;
    const int h   = tid >> 7;        // which N-half this thread reduces
    const int i   = tid & (TM_ - 1); // m index within tile / loader lane
    const int m   = m0 + i;

    if (tid < COUT_ * C_) sw[tid] = w[tid];
    if (tid < COUT_)      sb[tid] = bias[tid];

    // Per-channel exponent coefficient, log2e folded in: arg = k2 * (x - t)^2
    const float LOG2E = 1.4426950408889634f;
    float k2[C_];
#pragma unroll
    for (int c = 0; c < C_; c++) {
        float s = expf(sigma[c]);
        k2[c] = -(0.5f * LOG2E) / (s * s);
    }
    bool uniform = true;
#pragma unroll
    for (int c = 1; c < C_; c++) uniform &= (k2[c] == k2[0]);

    const float tm = t[b * M_ + m];
    // k2*(x-t)^2 = (k2*x^2) + U*x + T
    const float U = -2.0f * k2[0] * tm;
    const float T = k2[0] * tm * tm;

    float acc[C_];
#pragma unroll
    for (int c = 0; c < C_; c++) acc[c] = 0.0f;

    const int    nbase = h * (N_ / 2);
    const float* xb    = x + b * N_;
    const float* ybp   = y + (size_t)b * N_ * CIN_;
    const int    NTILES = (N_ / 2) / TN_;

    if (uniform) {
        // Fast path: one exp per (n,m), packed dual-FMA accumulation.
        unsigned long long a01 = 0ull, a23 = 0ull, a45 = 0ull, a67 = 0ull;
        for (int tile = 0; tile < NTILES; tile++) {
            const int n = nbase + tile * TN_ + i;
            float xv = xb[n];
            sxa[h][i] = make_float2(xv, k2[0] * xv * xv);
            const float* yp = ybp + (size_t)n * CIN_;
            float y0 = yp[0], y1 = yp[1], y2 = yp[2], y3 = yp[3];
            float y4 = yp[4], y5 = yp[5], y6 = yp[6];
            syA[h][i] = make_ulonglong2(pack2(1.0f, y0), pack2(y1, y2));
            syB[h][i] = make_ulonglong2(pack2(y3, y4), pack2(y5, y6));
            __syncthreads();
#pragma unroll 4
            for (int j = 0; j < TN_; j++) {
                float2 xa = sxa[h][j];                 // broadcast LDS.64
                float arg = fmaf(U, xa.x, T) + xa.y;
                float e   = ex2f(arg);
                unsigned long long ee = pack2(e, e);
                ulonglong2 ya = syA[h][j];             // broadcast LDS.128
                ulonglong2 yb = syB[h][j];
                a01 = fma2(ya.x, ee, a01);
                a23 = fma2(ya.y, ee, a23);
                a45 = fma2(yb.x, ee, a45);
                a67 = fma2(yb.y, ee, a67);
            }
            __syncthreads();
        }
        unpack2(a01, acc[0], acc[1]);
        unpack2(a23, acc[2], acc[3]);
        unpack2(a45, acc[4], acc[5]);
        unpack2(a67, acc[6], acc[7]);
    } else {
        // General path: per-channel exponent (correct for arbitrary sigma).
        for (int tile = 0; tile < NTILES; tile++) {
            const int n = nbase + tile * TN_ + i;
            float xv = xb[n];
            sxa[h][i] = make_float2(xv, k2[0] * xv * xv);
            const float* yp = ybp + (size_t)n * CIN_;
            float y0 = yp[0], y1 = yp[1], y2 = yp[2], y3 = yp[3];
            float y4 = yp[4], y5 = yp[5], y6 = yp[6];
            syA[h][i] = make_ulonglong2(pack2(1.0f, y0), pack2(y1, y2));
            syB[h][i] = make_ulonglong2(pack2(y3, y4), pack2(y5, y6));
            __syncthreads();
#pragma unroll 2
            for (int j = 0; j < TN_; j++) {
                float2 xa = sxa[h][j];
                float dd  = xa.x - tm;
                float dd2 = dd * dd;
                ulonglong2 ya = syA[h][j];
                ulonglong2 yb = syB[h][j];
                float yv[C_];
                unpack2(ya.x, yv[0], yv[1]);
                unpack2(ya.y, yv[2], yv[3]);
                unpack2(yb.x, yv[4], yv[5]);
                unpack2(yb.y, yv[6], yv[7]);
#pragma unroll
                for (int c = 0; c < C_; c++)
                    acc[c] = fmaf(yv[c], ex2f(k2[c] * dd2), acc[c]);
            }
            __syncthreads();
        }
    }

    // Combine the two N-halves, then fused epilogue.
    if (h == 1) {
#pragma unroll
        for (int c = 0; c < C_; c++) sacc[i][c] = acc[c];
    }
    __syncthreads();
    if (h == 0) {
#pragma unroll
        for (int c = 0; c < C_; c++) acc[c] += sacc[i][c];

        float density = acc[0];
        float inv = 1.0f / (density + EPS_);
        float feats[C_];
        feats[0] = density;
#pragma unroll
        for (int c = 1; c < C_; c++) feats[c] = acc[c] * inv;

        float* op = out + ((size_t)(b * M_ + m)) * COUT_;
#pragma unroll
        for (int og = 0; og < 4; og++) {
            float rr[4];
#pragma unroll
            for (int k = 0; k < 4; k++) {
                const int o = og * 4 + k;
                float s = sb[o];
#pragma unroll
                for (int c = 0; c < C_; c++)
                    s = fmaf(sw[o * C_ + c], feats[c], s);
                rr[k] = s;
            }
            *(float4*)(op + og * 4) = make_float4(rr[0], rr[1], rr[2], rr[3]);
        }
    }
}

extern "C" void kernel_launch(void* const* d_in, const int* in_sizes, int n_in,
                              void* d_out, int out_size) {
    (void)in_sizes; (void)n_in; (void)out_size;
    const float* x     = (const float*)d_in[0];
    const float* y     = (const float*)d_in[1];
    const float* t     = (const float*)d_in[2];
    const float* sigma = (const float*)d_in[3];
    const float* w     = (const float*)d_in[4];
    const float* bias  = (const float*)d_in[5];
    float* out = (float*)d_out;

    dim3 grid(M_ / TM_, B_);
    convdeepset_kernel<<<grid, THREADS_>>>(x, y, t, sigma, w, bias, out);
}

// round 5
// speedup vs baseline: 1.1193x; 1.1193x over previous
#include <cuda_runtime.h>

// Shapes fixed by the problem's setup_inputs.
#define B_     16
#define N_     1024
#define M_     1024
#define CIN_   7
#define C_     8
#define COUT_  16
#define TM_    128     // m-values per block
#define NQ_    256     // n's per quarter (N/4)
#define THREADS_ 512   // 4 quarters x 128 m-threads
#define EPS_   1e-8f

typedef unsigned long long ull;

__device__ __forceinline__ float ex2f(float v) {
    float r; asm("ex2.approx.f32 %0, %1;" : "=f"(r) : "f"(v)); return r;
}
__device__ __forceinline__ ull pack2(float lo, float hi) {
    ull r; asm("mov.b64 %0, {%1, %2};" : "=l"(r) : "f"(lo), "f"(hi)); return r;
}
__device__ __forceinline__ void unpack2(ull v, float& lo, float& hi) {
    asm("mov.b64 {%0, %1}, %2;" : "=f"(lo), "=f"(hi) : "l"(v));
}
// Packed dual-FMA / dual-ADD (Blackwell f32x2).
__device__ __forceinline__ ull fma2(ull a, ull b, ull c) {
    ull d; asm("fma.rn.f32x2 %0, %1, %2, %3;" : "=l"(d) : "l"(a), "l"(b), "l"(c));
    return d;
}
__device__ __forceinline__ ull add2(ull a, ull b) {
    ull d; asm("add.rn.f32x2 %0, %1, %2;" : "=l"(d) : "l"(a), "l"(b));
    return d;
}

// Shared-memory budget (static, <48KB), with aliasing:
//   [0,      8192)  sxq:  4 quarters x 128 float4 {x_j, x_j+1, q_j, q_j+1}
//   [8192,  24576)  syA:  4 x 256 ulonglong2  {1,y0 | y1,y2}
//   [24576, 40960)  syB:  4 x 256 ulonglong2  {y3,y4 | y5,y6}
//   [0,     12288)  sacc: 3 x 128 x 8 floats  (ALIASES sxq/syA; used post-loop)
//   [40960, 41536)  sw (128 floats) + sb (16 floats)
#define SMEM_BYTES (40960 + 576)

__global__ __launch_bounds__(THREADS_, 1)
void convdeepset_kernel(const float* __restrict__ x,     // [B, N]
                        const float* __restrict__ y,     // [B, N, CIN]
                        const float* __restrict__ t,     // [B, M]
                        const float* __restrict__ sigma, // [C]
                        const float* __restrict__ w,     // [COUT, C]
                        const float* __restrict__ bias,  // [COUT]
                        float* __restrict__ out)         // [B, M, COUT]
{
    __shared__ __align__(16) char smem_raw[SMEM_BYTES];
    float4*     sxq  = (float4*)smem_raw;                  // [4][128]
    ulonglong2* syA  = (ulonglong2*)(smem_raw + 8192);     // [4][256]
    ulonglong2* syB  = (ulonglong2*)(smem_raw + 24576);    // [4][256]
    float*      sacc = (float*)smem_raw;                   // [3][128][8] (aliased)
    float*      sw   = (float*)(smem_raw + 40960);
    float*      sb   = sw + COUT_ * C_;

    const int b   = blockIdx.y;
    const int m0  = blockIdx.x * TM_;
    const int tid = threadIdx.x;
    const int h   = tid >> 7;        // N-quarter this thread reduces
    const int i   = tid & (TM_ - 1); // m index within tile
    const int m   = m0 + i;

    if (tid < COUT_ * C_)                       sw[tid] = w[tid];
    if (tid >= 128 && tid < 128 + COUT_)        sb[tid - 128] = bias[tid - 128];

    // Per-channel exponent coefficient, log2e folded in: arg = k2 * (x - t)^2
    const float LOG2E = 1.4426950408889634f;
    float k2[C_];
#pragma unroll
    for (int c = 0; c < C_; c++) {
        float s = expf(sigma[c]);
        k2[c] = -(0.5f * LOG2E) / (s * s);
    }
    bool uniform = true;
#pragma unroll
    for (int c = 1; c < C_; c++) uniform &= (k2[c] == k2[0]);

    const float tm = t[b * M_ + m];
    // k2*(x-t)^2 = (k2*x^2) + U*x + T
    const float U = -2.0f * k2[0] * tm;
    const float T = k2[0] * tm * tm;
    const ull   UU = pack2(U, U);
    const ull   TT = pack2(T, T);

    const float* xb  = x + b * N_;
    const float* ybp = y + (size_t)b * N_ * CIN_;

    // ---- Load this quarter's tile (each thread loads 2 n's) ----
    float* xqf = (float*)(sxq + h * (NQ_ / 2));
#pragma unroll
    for (int r = 0; r < 2; r++) {
        const int l = i + r * TM_;          // 0..255 within quarter
        const int n = h * NQ_ + l;
        const float xv = xb[n];
        // packed pair layout: {x_j, x_j+1, q_j, q_j+1} per float4
        xqf[(l >> 1) * 4 + (l & 1)]     = xv;
        xqf[(l >> 1) * 4 + 2 + (l & 1)] = k2[0] * xv * xv;
        const float* yp = ybp + (size_t)n * CIN_;
        float y0 = yp[0], y1 = yp[1], y2 = yp[2], y3 = yp[3];
        float y4 = yp[4], y5 = yp[5], y6 = yp[6];
        syA[h * NQ_ + l] = make_ulonglong2(pack2(1.0f, y0), pack2(y1, y2));
        syB[h * NQ_ + l] = make_ulonglong2(pack2(y3, y4), pack2(y5, y6));
    }
    __syncthreads();

    float acc[C_];
#pragma unroll
    for (int c = 0; c < C_; c++) acc[c] = 0.0f;

    if (uniform) {
        // Fast path: packed dual-arg + dual-FMA accumulation, 2 n's per step.
        const ulonglong2* xq = (const ulonglong2*)(sxq + h * (NQ_ / 2));
        const ulonglong2* yA = syA + h * NQ_;
        const ulonglong2* yB = syB + h * NQ_;
        ull a01 = 0ull, a23 = 0ull, a45 = 0ull, a67 = 0ull;
#pragma unroll 4
        for (int jj = 0; jj < NQ_ / 2; jj++) {
            ulonglong2 v = xq[jj];                  // {x_j,x_j1 | q_j,q_j1}
            ull args = add2(fma2(UU, v.x, TT), v.y);
            float f0, f1; unpack2(args, f0, f1);
            float e0 = ex2f(f0), e1 = ex2f(f1);
            ull ee0 = pack2(e0, e0), ee1 = pack2(e1, e1);
            ulonglong2 A0 = yA[2 * jj],     B0 = yB[2 * jj];
            ulonglong2 A1 = yA[2 * jj + 1], B1 = yB[2 * jj + 1];
            a01 = fma2(A0.x, ee0, a01);
            a23 = fma2(A0.y, ee0, a23);
            a45 = fma2(B0.x, ee0, a45);
            a67 = fma2(B0.y, ee0, a67);
            a01 = fma2(A1.x, ee1, a01);
            a23 = fma2(A1.y, ee1, a23);
            a45 = fma2(B1.x, ee1, a45);
            a67 = fma2(B1.y, ee1, a67);
        }
        unpack2(a01, acc[0], acc[1]);
        unpack2(a23, acc[2], acc[3]);
        unpack2(a45, acc[4], acc[5]);
        unpack2(a67, acc[6], acc[7]);
    } else {
        // General path (arbitrary sigma): per-channel exponent.
        const ulonglong2* xq = (const ulonglong2*)(sxq + h * (NQ_ / 2));
        const ulonglong2* yA = syA + h * NQ_;
        const ulonglong2* yB = syB + h * NQ_;
        for (int jj = 0; jj < NQ_ / 2; jj++) {
            ulonglong2 v = xq[jj];
            float x0, x1, q0, q1;
            unpack2(v.x, x0, x1); unpack2(v.y, q0, q1);
            (void)q0; (void)q1;
#pragma unroll
            for (int s = 0; s < 2; s++) {
                const float xv = s ? x1 : x0;
                const float dd = xv - tm;
                const float dd2 = dd * dd;
                ulonglong2 ya = yA[2 * jj + s];
                ulonglong2 yb = yB[2 * jj + s];
                float yv[C_];
                unpack2(ya.x, yv[0], yv[1]);
                unpack2(ya.y, yv[2], yv[3]);
                unpack2(yb.x, yv[4], yv[5]);
                unpack2(yb.y, yv[6], yv[7]);
#pragma unroll
                for (int c = 0; c < C_; c++)
                    acc[c] = fmaf(yv[c], ex2f(k2[c] * dd2), acc[c]);
            }
        }
    }

    // ---- Combine the 4 quarters (sacc aliases the dead tile region) ----
    __syncthreads();
    if (h > 0) {
#pragma unroll
        for (int c = 0; c < C_; c++)
            sacc[((h - 1) * TM_ + i) * C_ + c] = acc[c];
    }
    __syncthreads();
    if (h == 0) {
#pragma unroll
        for (int p = 0; p < 3; p++)
#pragma unroll
            for (int c = 0; c < C_; c++)
                acc[c] += sacc[(p * TM_ + i) * C_ + c];

        float density = acc[0];
        float inv = 1.0f / (density + EPS_);
        float feats[C_];
        feats[0] = density;
#pragma unroll
        for (int c = 1; c < C_; c++) feats[c] = acc[c] * inv;

        float* op = out + ((size_t)(b * M_ + m)) * COUT_;
#pragma unroll
        for (int og = 0; og < 4; og++) {
            float rr[4];
#pragma unroll
            for (int k = 0; k < 4; k++) {
                const int o = og * 4 + k;
                float s = sb[o];
#pragma unroll
                for (int c = 0; c < C_; c++)
                    s = fmaf(sw[o * C_ + c], feats[c], s);
                rr[k] = s;
            }
            *(float4*)(op + og * 4) = make_float4(rr[0], rr[1], rr[2], rr[3]);
        }
    }
}

extern "C" void kernel_launch(void* const* d_in, const int* in_sizes, int n_in,
                              void* d_out, int out_size) {
    (void)in_sizes; (void)n_in; (void)out_size;
    const float* x     = (const float*)d_in[0];
    const float* y     = (const float*)d_in[1];
    const float* t     = (const float*)d_in[2];
    const float* sigma = (const float*)d_in[3];
    const float* w     = (const float*)d_in[4];
    const float* bias  = (const float*)d_in[5];
    float* out = (float*)d_out;

    dim3 grid(M_ / TM_, B_);
    convdeepset_kernel<<<grid, THREADS_>>>(x, y, t, sigma, w, bias, out);
}

// round 6
// speedup vs baseline: 1.1386x; 1.0173x over previous
#include <cuda_runtime.h>

// Shapes fixed by the problem's setup_inputs.
#define B_     16
#define N_     1024
#define M_     1024
#define CIN_   7
#define C_     8
#define COUT_  16
#define TM_    128     // m-values per block (64 threads x 2 m each)
#define NG_    128     // n's per group (N/8)
#define THREADS_ 512   // 8 n-groups x 64 m-threads
#define EPS_   1e-8f

typedef unsigned long long ull;

__device__ __forceinline__ float ex2f(float v) {
    float r; asm("ex2.approx.f32 %0, %1;" : "=f"(r) : "f"(v)); return r;
}
__device__ __forceinline__ ull pack2(float lo, float hi) {
    ull r; asm("mov.b64 %0, {%1, %2};" : "=l"(r) : "f"(lo), "f"(hi)); return r;
}
__device__ __forceinline__ void unpack2(ull v, float& lo, float& hi) {
    asm("mov.b64 {%0, %1}, %2;" : "=f"(lo), "=f"(hi) : "l"(v));
}
// Packed dual-FMA / dual-ADD (Blackwell f32x2).
__device__ __forceinline__ ull fma2(ull a, ull b, ull c) {
    ull d; asm("fma.rn.f32x2 %0, %1, %2, %3;" : "=l"(d) : "l"(a), "l"(b), "l"(c));
    return d;
}
__device__ __forceinline__ ull add2(ull a, ull b) {
    ull d; asm("add.rn.f32x2 %0, %1, %2;" : "=l"(d) : "l"(a), "l"(b));
    return d;
}

// Shared memory (static, <48KB), with aliasing:
//   [0,      8192)  sxq:  512 float4 {x_2j, x_2j+1, q_2j, q_2j+1}  (8 groups x 64)
//   [8192,  24576)  syA:  1024 ulonglong2  {1,y0 | y1,y2}
//   [24576, 40960)  syB:  1024 ulonglong2  {y3,y4 | y5,y6}
//   [0,     28672)  sacc: 7 groups x 64 thr x 2 m x 8 c floats (ALIASES tile; post-loop)
//   [40960, 41536)  sw (128 floats) + sb (16 floats)
#define SMEM_BYTES (40960 + 576)

__global__ __launch_bounds__(THREADS_, 1)
void convdeepset_kernel(const float* __restrict__ x,     // [B, N]
                        const float* __restrict__ y,     // [B, N, CIN]
                        const float* __restrict__ t,     // [B, M]
                        const float* __restrict__ sigma, // [C]
                        const float* __restrict__ w,     // [COUT, C]
                        const float* __restrict__ bias,  // [COUT]
                        float* __restrict__ out)         // [B, M, COUT]
{
    __shared__ __align__(16) char smem_raw[SMEM_BYTES];
    float4*     sxq  = (float4*)smem_raw;                  // [512]
    ulonglong2* syA  = (ulonglong2*)(smem_raw + 8192);     // [1024]
    ulonglong2* syB  = (ulonglong2*)(smem_raw + 24576);    // [1024]
    float*      sacc = (float*)smem_raw;                   // aliased, post-loop
    float*      sw   = (float*)(smem_raw + 40960);
    float*      sb   = sw + COUT_ * C_;

    const int b   = blockIdx.y;
    const int m0  = blockIdx.x * TM_;
    const int tid = threadIdx.x;
    const int g   = tid >> 6;        // n-group (0..7)
    const int i   = tid & 63;        // m-lane within tile
    const int mA  = m0 + i;          // first m this thread owns
    const int mB  = m0 + 64 + i;     // second m

    if (tid < COUT_ * C_)                sw[tid] = w[tid];
    if (tid >= 128 && tid < 128 + COUT_) sb[tid - 128] = bias[tid - 128];

    // Per-channel exponent coefficient, log2e folded: arg = k2*(x-t)^2
    const float LOG2E = 1.4426950408889634f;
    float k2[C_];
#pragma unroll
    for (int c = 0; c < C_; c++) {
        float s = expf(sigma[c]);
        k2[c] = -(0.5f * LOG2E) / (s * s);
    }
    bool uniform = true;
#pragma unroll
    for (int c = 1; c < C_; c++) uniform &= (k2[c] == k2[0]);

    const float tmA = t[b * M_ + mA];
    const float tmB = t[b * M_ + mB];
    // k2*(x-t)^2 = (k2*x^2) + U*x + T
    const float UA = -2.0f * k2[0] * tmA, TA = k2[0] * tmA * tmA;
    const float UB = -2.0f * k2[0] * tmB, TB = k2[0] * tmB * tmB;
    const ull UUA = pack2(UA, UA), TTA = pack2(TA, TA);
    const ull UUB = pack2(UB, UB), TTB = pack2(TB, TB);

    const float* xb  = x + b * N_;
    const float* ybp = y + (size_t)b * N_ * CIN_;

    // ---- Cooperative tile load: thread tid owns n-pair (2*tid, 2*tid+1) ----
    {
        const int n0 = 2 * tid, n1 = n0 + 1;
        const float x0 = xb[n0], x1 = xb[n1];
        sxq[tid] = make_float4(x0, x1, k2[0] * x0 * x0, k2[0] * x1 * x1);
        const float* yp0 = ybp + (size_t)n0 * CIN_;
        const float* yp1 = ybp + (size_t)n1 * CIN_;
        syA[n0] = make_ulonglong2(pack2(1.0f, yp0[0]), pack2(yp0[1], yp0[2]));
        syB[n0] = make_ulonglong2(pack2(yp0[3], yp0[4]), pack2(yp0[5], yp0[6]));
        syA[n1] = make_ulonglong2(pack2(1.0f, yp1[0]), pack2(yp1[1], yp1[2]));
        syB[n1] = make_ulonglong2(pack2(yp1[3], yp1[4]), pack2(yp1[5], yp1[6]));
    }
    __syncthreads();

    // Accumulators: [m(2)][channel-pair(4)]
    ull accA[4] = {0ull, 0ull, 0ull, 0ull};
    ull accB[4] = {0ull, 0ull, 0ull, 0ull};

    const float4*     xq = sxq + g * (NG_ / 2);
    const ulonglong2* yA = syA + g * NG_;
    const ulonglong2* yB = syB + g * NG_;

    if (uniform) {
#pragma unroll 4
        for (int jj = 0; jj < NG_ / 2; jj++) {
            float4 v = xq[jj];                     // {x0,x1,q0,q1}
            ull xx = pack2(v.x, v.y);
            ull qq = pack2(v.z, v.w);
            // exponent args for both j's, per m
            ull argsA = add2(fma2(UUA, xx, TTA), qq);
            ull argsB = add2(fma2(UUB, xx, TTB), qq);
            float fA0, fA1, fB0, fB1;
            unpack2(argsA, fA0, fA1);
            unpack2(argsB, fB0, fB1);
            float eA0 = ex2f(fA0), eA1 = ex2f(fA1);
            float eB0 = ex2f(fB0), eB1 = ex2f(fB1);
            ull eeA0 = pack2(eA0, eA0), eeA1 = pack2(eA1, eA1);
            ull eeB0 = pack2(eB0, eB0), eeB1 = pack2(eB1, eB1);

            ulonglong2 A0 = yA[2 * jj],     Bv0 = yB[2 * jj];
            ulonglong2 A1 = yA[2 * jj + 1], Bv1 = yB[2 * jj + 1];

            accA[0] = fma2(A0.x,  eeA0, accA[0]);
            accA[1] = fma2(A0.y,  eeA0, accA[1]);
            accA[2] = fma2(Bv0.x, eeA0, accA[2]);
            accA[3] = fma2(Bv0.y, eeA0, accA[3]);
            accB[0] = fma2(A0.x,  eeB0, accB[0]);
            accB[1] = fma2(A0.y,  eeB0, accB[1]);
            accB[2] = fma2(Bv0.x, eeB0, accB[2]);
            accB[3] = fma2(Bv0.y, eeB0, accB[3]);

            accA[0] = fma2(A1.x,  eeA1, accA[0]);
            accA[1] = fma2(A1.y,  eeA1, accA[1]);
            accA[2] = fma2(Bv1.x, eeA1, accA[2]);
            accA[3] = fma2(Bv1.y, eeA1, accA[3]);
            accB[0] = fma2(A1.x,  eeB1, accB[0]);
            accB[1] = fma2(A1.y,  eeB1, accB[1]);
            accB[2] = fma2(Bv1.x, eeB1, accB[2]);
            accB[3] = fma2(Bv1.y, eeB1, accB[3]);
        }
    } else {
        // General path (arbitrary sigma): per-channel exponent, both m's.
        for (int jj = 0; jj < NG_ / 2; jj++) {
            float4 v = xq[jj];
#pragma unroll
            for (int s = 0; s < 2; s++) {
                const float xv = s ? v.y : v.x;
                const float dA = xv - tmA, dA2 = dA * dA;
                const float dB = xv - tmB, dB2 = dB * dB;
                ulonglong2 ya = yA[2 * jj + s];
                ulonglong2 yb = yB[2 * jj + s];
                float yv[C_];
                unpack2(ya.x, yv[0], yv[1]);
                unpack2(ya.y, yv[2], yv[3]);
                unpack2(yb.x, yv[4], yv[5]);
                unpack2(yb.y, yv[6], yv[7]);
#pragma unroll
                for (int c = 0; c < C_; c++) {
                    float eA = ex2f(k2[c] * dA2);
                    float eB = ex2f(k2[c] * dB2);
                    float lo, hi; unpack2(accA[c >> 1], lo, hi);
                    if (c & 1) hi = fmaf(yv[c], eA, hi); else lo = fmaf(yv[c], eA, lo);
                    accA[c >> 1] = pack2(lo, hi);
                    unpack2(accB[c >> 1], lo, hi);
                    if (c & 1) hi = fmaf(yv[c], eB, hi); else lo = fmaf(yv[c], eB, lo);
                    accB[c >> 1] = pack2(lo, hi);
                }
            }
        }
    }

    // ---- Reduce the 8 n-group partials (sacc aliases the dead tile) ----
    __syncthreads();
    if (g > 0) {
        float* dst = sacc + (((g - 1) * 64 + i) * 2) * C_;
        ulonglong2* d2 = (ulonglong2*)dst;
        d2[0] = make_ulonglong2(accA[0], accA[1]);
        d2[1] = make_ulonglong2(accA[2], accA[3]);
        d2[2] = make_ulonglong2(accB[0], accB[1]);
        d2[3] = make_ulonglong2(accB[2], accB[3]);
    }
    __syncthreads();
    if (g == 0) {
#pragma unroll
        for (int p = 0; p < 7; p++) {
            const ulonglong2* s2 = (const ulonglong2*)(sacc + ((p * 64 + i) * 2) * C_);
            ulonglong2 r0 = s2[0], r1 = s2[1], r2 = s2[2], r3 = s2[3];
            accA[0] = add2(accA[0], r0.x);
            accA[1] = add2(accA[1], r0.y);
            accA[2] = add2(accA[2], r1.x);
            accA[3] = add2(accA[3], r1.y);
            accB[0] = add2(accB[0], r2.x);
            accB[1] = add2(accB[1], r2.y);
            accB[2] = add2(accB[2], r3.x);
            accB[3] = add2(accB[3], r3.y);
        }

        // Fused epilogue for both m's.
#pragma unroll
        for (int s = 0; s < 2; s++) {
            const ull* acc = s ? accB : accA;
            float a[C_];
            unpack2(acc[0], a[0], a[1]);
            unpack2(acc[1], a[2], a[3]);
            unpack2(acc[2], a[4], a[5]);
            unpack2(acc[3], a[6], a[7]);
            float density = a[0];
            float inv = 1.0f / (density + EPS_);
            float feats[C_];
            feats[0] = density;
#pragma unroll
            for (int c = 1; c < C_; c++) feats[c] = a[c] * inv;

            const int m = s ? mB : mA;
            float* op = out + ((size_t)(b * M_ + m)) * COUT_;
#pragma unroll
            for (int og = 0; og < 4; og++) {
                float rr[4];
#pragma unroll
                for (int k = 0; k < 4; k++) {
                    const int o = og * 4 + k;
                    float sacc0 = sb[o];
#pragma unroll
                    for (int c = 0; c < C_; c++)
                        sacc0 = fmaf(sw[o * C_ + c], feats[c], sacc0);
                    rr[k] = sacc0;
                }
                *(float4*)(op + og * 4) = make_float4(rr[0], rr[1], rr[2], rr[3]);
            }
        }
    }
}

extern "C" void kernel_launch(void* const* d_in, const int* in_sizes, int n_in,
                              void* d_out, int out_size) {
    (void)in_sizes; (void)n_in; (void)out_size;
    const float* x     = (const float*)d_in[0];
    const float* y     = (const float*)d_in[1];
    const float* t     = (const float*)d_in[2];
    const float* sigma = (const float*)d_in[3];
    const float* w     = (const float*)d_in[4];
    const float* bias  = (const float*)d_in[5];
    float* out = (float*)d_out;

    dim3 grid(M_ / TM_, B_);
    convdeepset_kernel<<<grid, THREADS_>>>(x, y, t, sigma, w, bias, out);
}